// round 1
// baseline (speedup 1.0000x reference)
#include <cuda_runtime.h>
#include <cstdint>
#include <math.h>

// Problem: out[bh,q,d] = softmax_k( (Q@K^T)[bh,q,k] * scale[q,k] ) @ V, then * dropout_p
// BH=32, S=2048, D=128, fp32.
// Flash-attention structure: one CTA per (bh, 64-row q tile); stream 64-row k tiles,
// online softmax with per-element scale tile applied pre-softmax.

constexpr int kBH = 32;
constexpr int kS  = 2048;
constexpr int kD  = 128;
constexpr int kBQ = 64;
constexpr int kBK = 64;
constexpr int kThreads = 256;
constexpr int kQKPad = kD + 1;  // padded row stride (floats) for Q/K: 2-way max LDS conflict

struct Smem {
    float Q[kBQ * kQKPad];   // padded
    float K[kBK * kQKPad];   // padded
    float V[kBK * kD];       // unpadded, float4-friendly
    float SC[kBQ * kBK];     // scale tile
    float P[kBQ * kBK];      // softmax probabilities
};
constexpr int kSmemBytes = (int)sizeof(Smem);

// dropout_p arrives as a 1-element tensor of unknown dtype (python scalar 1).
// Decode the 32-bit word: tiny-magnitude bit patterns are int32, else float32 bits.
__device__ __forceinline__ float decode_scalar(const void* p) {
    const int w = *reinterpret_cast<const int*>(p);
    if (w > -(1 << 23) && w < (1 << 23)) return (float)w;  // int32 path (incl. 0, 1)
    return __int_as_float(w);                              // float32 path (1.0f etc.)
}

__global__ __launch_bounds__(kThreads, 1)
void flash_attn_kernel(const float* __restrict__ q,
                       const float* __restrict__ k,
                       const float* __restrict__ v,
                       const float* __restrict__ sf,
                       const void*  __restrict__ dropout_p,
                       float* __restrict__ out) {
    extern __shared__ char smem_raw[];
    Smem& sm = *reinterpret_cast<Smem*>(smem_raw);

    const int tid = (int)threadIdx.x;
    const int tx = tid & 15;   // 16 thread-columns
    const int ty = tid >> 4;   // 16 thread-rows (lanes 0-15 / 16-31 of a warp share ty)
    const int qt = (int)blockIdx.x;
    const int bh = (int)blockIdx.y;

    const float* qg = q + ((size_t)bh * kS + (size_t)qt * kBQ) * kD;
    const float* kg = k + (size_t)bh * kS * kD;
    const float* vg = v + (size_t)bh * kS * kD;
    const float* sg = sf + (size_t)qt * kBQ * kS;

    // ---- Load Q tile into padded smem (float4 LDG, scalar STS due to pad) ----
    #pragma unroll
    for (int idx = tid; idx < kBQ * kD / 4; idx += kThreads) {
        const int r  = idx >> 5;        // / (kD/4 == 32)
        const int c4 = idx & 31;
        const float4 val = reinterpret_cast<const float4*>(qg)[idx];
        float* dst = &sm.Q[r * kQKPad + c4 * 4];
        dst[0] = val.x; dst[1] = val.y; dst[2] = val.z; dst[3] = val.w;
    }

    // Per-thread state: 4 q rows (ty), 8 output columns (tx) -> O[4][8]
    float O[4][8];
    #pragma unroll
    for (int i = 0; i < 4; ++i)
        #pragma unroll
        for (int j = 0; j < 8; ++j) O[i][j] = 0.f;
    float m[4] = {-INFINITY, -INFINITY, -INFINITY, -INFINITY};
    float l[4] = {0.f, 0.f, 0.f, 0.f};

    for (int kt = 0; kt < kS / kBK; ++kt) {
        __syncthreads();  // previous iteration's P/V/SC reads complete (also covers Q load on iter 0)

        // ---- Load K tile (padded), V tile (float4 direct), scale tile ----
        const float* kgt = kg + (size_t)kt * kBK * kD;
        #pragma unroll
        for (int idx = tid; idx < kBK * kD / 4; idx += kThreads) {
            const int r  = idx >> 5;
            const int c4 = idx & 31;
            const float4 val = reinterpret_cast<const float4*>(kgt)[idx];
            float* dst = &sm.K[r * kQKPad + c4 * 4];
            dst[0] = val.x; dst[1] = val.y; dst[2] = val.z; dst[3] = val.w;
        }
        const float4* vgt = reinterpret_cast<const float4*>(vg + (size_t)kt * kBK * kD);
        #pragma unroll
        for (int idx = tid; idx < kBK * kD / 4; idx += kThreads)
            reinterpret_cast<float4*>(sm.V)[idx] = vgt[idx];
        const float* sgt = sg + (size_t)kt * kBK;
        #pragma unroll
        for (int idx = tid; idx < kBQ * kBK / 4; idx += kThreads) {
            const int r  = idx >> 4;    // / (kBK/4 == 16)
            const int c4 = idx & 15;
            reinterpret_cast<float4*>(sm.SC)[idx] =
                *reinterpret_cast<const float4*>(sgt + (size_t)r * kS + c4 * 4);
        }
        __syncthreads();

        // ---- S = Q @ K^T  (4x4 register tile per thread) ----
        float acc[4][4];
        #pragma unroll
        for (int i = 0; i < 4; ++i)
            #pragma unroll
            for (int j = 0; j < 4; ++j) acc[i][j] = 0.f;

        const float* qrow0 = &sm.Q[(ty * 4) * kQKPad];
        const float* krow0 = &sm.K[(tx * 4) * kQKPad];
        #pragma unroll 8
        for (int d = 0; d < kD; ++d) {
            float qf[4], kf[4];
            #pragma unroll
            for (int i = 0; i < 4; ++i) qf[i] = qrow0[i * kQKPad + d];
            #pragma unroll
            for (int j = 0; j < 4; ++j) kf[j] = krow0[j * kQKPad + d];
            #pragma unroll
            for (int i = 0; i < 4; ++i)
                #pragma unroll
                for (int j = 0; j < 4; ++j)
                    acc[i][j] = fmaf(qf[i], kf[j], acc[i][j]);
        }

        // ---- Apply per-element scale, online softmax (rows reduced over 16 lanes) ----
        #pragma unroll
        for (int i = 0; i < 4; ++i) {
            const float4 sc = *reinterpret_cast<const float4*>(&sm.SC[(ty * 4 + i) * kBK + tx * 4]);
            acc[i][0] *= sc.x; acc[i][1] *= sc.y; acc[i][2] *= sc.z; acc[i][3] *= sc.w;

            float rmax = fmaxf(fmaxf(acc[i][0], acc[i][1]), fmaxf(acc[i][2], acc[i][3]));
            #pragma unroll
            for (int off = 8; off; off >>= 1)
                rmax = fmaxf(rmax, __shfl_xor_sync(0xffffffffu, rmax, off));

            const float mnew  = fmaxf(m[i], rmax);
            const float alpha = __expf(m[i] - mnew);

            float pr[4];
            float rsum = 0.f;
            #pragma unroll
            for (int j = 0; j < 4; ++j) { pr[j] = __expf(acc[i][j] - mnew); rsum += pr[j]; }
            #pragma unroll
            for (int off = 8; off; off >>= 1)
                rsum += __shfl_xor_sync(0xffffffffu, rsum, off);

            l[i] = l[i] * alpha + rsum;
            m[i] = mnew;
            #pragma unroll
            for (int j2 = 0; j2 < 8; ++j2) O[i][j2] *= alpha;

            *reinterpret_cast<float4*>(&sm.P[(ty * 4 + i) * kBK + tx * 4]) =
                make_float4(pr[0], pr[1], pr[2], pr[3]);
        }
        __syncthreads();

        // ---- O += P @ V  (4 q rows x 8 d cols per thread) ----
        const float* prow0 = &sm.P[(ty * 4) * kBK];
        #pragma unroll 4
        for (int kk = 0; kk < kBK; ++kk) {
            const float4 v0 = *reinterpret_cast<const float4*>(&sm.V[kk * kD + tx * 8]);
            const float4 v1 = *reinterpret_cast<const float4*>(&sm.V[kk * kD + tx * 8 + 4]);
            float pf[4];
            #pragma unroll
            for (int i = 0; i < 4; ++i) pf[i] = prow0[i * kBK + kk];
            #pragma unroll
            for (int i = 0; i < 4; ++i) {
                O[i][0] = fmaf(pf[i], v0.x, O[i][0]);
                O[i][1] = fmaf(pf[i], v0.y, O[i][1]);
                O[i][2] = fmaf(pf[i], v0.z, O[i][2]);
                O[i][3] = fmaf(pf[i], v0.w, O[i][3]);
                O[i][4] = fmaf(pf[i], v1.x, O[i][4]);
                O[i][5] = fmaf(pf[i], v1.y, O[i][5]);
                O[i][6] = fmaf(pf[i], v1.z, O[i][6]);
                O[i][7] = fmaf(pf[i], v1.w, O[i][7]);
            }
        }
    }

    // ---- Epilogue: normalize by row sum, apply dropout_p scalar, store ----
    const float dp = decode_scalar(dropout_p);
    #pragma unroll
    for (int i = 0; i < 4; ++i) {
        const float inv = dp / l[i];
        const size_t base = ((size_t)bh * kS + (size_t)qt * kBQ + (size_t)(ty * 4 + i)) * kD + tx * 8;
        float4 o0 = make_float4(O[i][0] * inv, O[i][1] * inv, O[i][2] * inv, O[i][3] * inv);
        float4 o1 = make_float4(O[i][4] * inv, O[i][5] * inv, O[i][6] * inv, O[i][7] * inv);
        *reinterpret_cast<float4*>(out + base)     = o0;
        *reinterpret_cast<float4*>(out + base + 4) = o1;
    }
}

extern "C" void kernel_launch(void* const* d_in, const int* in_sizes, int n_in,
                              void* d_out, int out_size) {
    const float* q  = (const float*)d_in[0];
    const float* k  = (const float*)d_in[1];
    const float* v  = (const float*)d_in[2];
    const float* sf = (const float*)d_in[3];
    const void*  dp = d_in[4];
    float* out = (float*)d_out;

    (void)in_sizes; (void)n_in; (void)out_size;

    cudaFuncSetAttribute(flash_attn_kernel,
                         cudaFuncAttributeMaxDynamicSharedMemorySize, kSmemBytes);
    dim3 grid(kS / kBQ, kBH);   // 32 q-tiles x 32 batch-heads = 1024 CTAs
    flash_attn_kernel<<<grid, kThreads, kSmemBytes>>>(q, k, v, sf, dp, out);
}

// round 3
// speedup vs baseline: 3.2591x; 3.2591x over previous
#include <cuda_runtime.h>
#include <cuda_bf16.h>
#include <cstdint>
#include <math.h>

// ============================================================
// Flash attention, per-element scale, mma.sync m16n8k16 bf16
// (hi/lo 3-term compensation), register accumulators.
// BH=32, S=2048, D=128. CTA: 128 q rows x 1 bh, 8 warps.
// Target-neutral PTX only (no tcgen05 — ptxas target is sm_103 base).
// ============================================================

constexpr int kS = 2048, kD = 128, kBQ = 128, kBK = 64;
constexpr int kThreads = 256;
constexpr int kIters = kS / kBK;         // 32

// K/V smem: bf16, rows padded to 136 elems (272B) for conflict-free ldmatrix
constexpr int kKVStrideB = 272;
constexpr int kKVTileB   = 64 * kKVStrideB;     // 17408
constexpr int SM_KHI = 0;
constexpr int SM_KLO = SM_KHI + kKVTileB;
constexpr int SM_VHI = SM_KLO + kKVTileB;
constexpr int SM_VLO = SM_VHI + kKVTileB;
constexpr int kScStride = 68;                    // floats (272B, 16B aligned)
constexpr int SM_SC  = SM_VLO + kKVTileB;        // 128 x 68 fp32 = 34816
constexpr int kSmemBytes = SM_SC + 128 * kScStride * 4;   // 104448

__device__ __forceinline__ uint32_t smem_u32(const void* p) {
    uint32_t a;
    asm("{ .reg .u64 t; cvta.to.shared.u64 t, %1; cvt.u32.u64 %0, t; }" : "=r"(a) : "l"(p));
    return a;
}

__device__ __forceinline__ void ldsm_x4(uint32_t& r0, uint32_t& r1, uint32_t& r2, uint32_t& r3,
                                        uint32_t addr) {
    asm volatile("ldmatrix.sync.aligned.m8n8.x4.shared.b16 {%0,%1,%2,%3}, [%4];"
        : "=r"(r0), "=r"(r1), "=r"(r2), "=r"(r3) : "r"(addr));
}
__device__ __forceinline__ void ldsm_x4_t(uint32_t& r0, uint32_t& r1, uint32_t& r2, uint32_t& r3,
                                          uint32_t addr) {
    asm volatile("ldmatrix.sync.aligned.m8n8.x4.trans.shared.b16 {%0,%1,%2,%3}, [%4];"
        : "=r"(r0), "=r"(r1), "=r"(r2), "=r"(r3) : "r"(addr));
}
// D += A(16x16 bf16) * B(16x8 bf16), fp32 accumulate
__device__ __forceinline__ void mma_bf16(float* d, const uint32_t* a, uint32_t b0, uint32_t b1) {
    asm volatile("mma.sync.aligned.m16n8k16.row.col.f32.bf16.bf16.f32 "
        "{%0,%1,%2,%3}, {%4,%5,%6,%7}, {%8,%9}, {%0,%1,%2,%3};"
        : "+f"(d[0]), "+f"(d[1]), "+f"(d[2]), "+f"(d[3])
        : "r"(a[0]), "r"(a[1]), "r"(a[2]), "r"(a[3]), "r"(b0), "r"(b1));
}

__device__ __forceinline__ uint32_t packbf(float a, float b) {
    __nv_bfloat162 t = __floats2bfloat162_rn(a, b);
    return *reinterpret_cast<uint32_t*>(&t);
}
__device__ __forceinline__ void split2(float a, float b, uint32_t& hi, uint32_t& lo) {
    __nv_bfloat16 ah = __float2bfloat16(a), bh = __float2bfloat16(b);
    __nv_bfloat162 h; h.x = ah; h.y = bh;
    hi = *reinterpret_cast<uint32_t*>(&h);
    lo = packbf(a - __bfloat162float(ah), b - __bfloat162float(bh));
}

__device__ __forceinline__ float decode_scalar(const void* p) {
    const int w = *reinterpret_cast<const int*>(p);
    if (w > -(1 << 23) && w < (1 << 23)) return (float)w;
    return __int_as_float(w);
}

__global__ __launch_bounds__(kThreads, 1)
void flash_mma_kernel(const float* __restrict__ q,
                      const float* __restrict__ k,
                      const float* __restrict__ v,
                      const float* __restrict__ sf,
                      const void*  __restrict__ dropout_p,
                      float* __restrict__ out) {
    extern __shared__ char smem[];
    const uint32_t sb = smem_u32(smem);
    const int tid  = (int)threadIdx.x;
    const int wid  = tid >> 5;
    const int lane = tid & 31;
    const int g    = lane >> 2;          // fragment row within 8
    const int t    = lane & 3;           // fragment col pair
    const int qt = (int)blockIdx.x;
    const int bh = (int)blockIdx.y;

    const float* qg = q + ((size_t)bh * kS + (size_t)qt * kBQ) * kD;
    const float* kg = k + (size_t)bh * kS * kD;
    const float* vg = v + (size_t)bh * kS * kD;
    const float* sg = sf + (size_t)(qt * kBQ) * kS;

    // ---- Q fragments (hi/lo), loaded once from gmem into registers ----
    // A-frag reg order for m16n8k16: a0=(g,2t), a1=(g+8,2t), a2=(g,2t+8), a3=(g+8,2t+8)
    uint32_t qhi[8][4], qlo[8][4];
    {
        const float* rq0 = qg + (size_t)(wid * 16 + g) * kD;
        const float* rq8 = rq0 + 8 * kD;
        #pragma unroll
        for (int ks = 0; ks < 8; ++ks) {
            const int c = ks * 16 + 2 * t;
            const float2 f0 = *reinterpret_cast<const float2*>(rq0 + c);
            const float2 f1 = *reinterpret_cast<const float2*>(rq8 + c);
            const float2 f2 = *reinterpret_cast<const float2*>(rq0 + c + 8);
            const float2 f3 = *reinterpret_cast<const float2*>(rq8 + c + 8);
            split2(f0.x, f0.y, qhi[ks][0], qlo[ks][0]);
            split2(f1.x, f1.y, qhi[ks][1], qlo[ks][1]);
            split2(f2.x, f2.y, qhi[ks][2], qlo[ks][2]);
            split2(f3.x, f3.y, qhi[ks][3], qlo[ks][3]);
        }
    }

    // O accumulators: 16 n-tiles (d = 0..127), C-frag layout
    float oacc[16][4];
    #pragma unroll
    for (int n = 0; n < 16; ++n)
        #pragma unroll
        for (int c = 0; c < 4; ++c) oacc[n][c] = 0.f;
    float m0 = -INFINITY, m1 = -INFINITY, l0 = 0.f, l1 = 0.f;

    // ldmatrix lane-address components
    const int w8 = lane & 7;
    const int b3 = (lane >> 3) & 1;
    const int b4 = (lane >> 4) & 1;

    for (int kt = 0; kt < kIters; ++kt) {
        __syncthreads();   // previous iteration finished reading smem

        // ---- cooperative loads: K,V -> bf16 hi/lo smem; SC -> fp32 smem ----
        const float* kgt = kg + (size_t)kt * kBK * kD;
        const float* vgt = vg + (size_t)kt * kBK * kD;
        #pragma unroll
        for (int it = 0; it < 8; ++it) {
            const int idx = it * kThreads + tid;           // 2048 float4
            const int r = idx >> 5, c = (idx & 31) << 2;
            const int so = r * kKVStrideB + c * 2;
            {
                const float4 x = reinterpret_cast<const float4*>(kgt)[idx];
                uint32_t h0, lo0, h1, lo1;
                split2(x.x, x.y, h0, lo0);
                split2(x.z, x.w, h1, lo1);
                *reinterpret_cast<uint2*>(smem + SM_KHI + so) = make_uint2(h0, h1);
                *reinterpret_cast<uint2*>(smem + SM_KLO + so) = make_uint2(lo0, lo1);
            }
            {
                const float4 x = reinterpret_cast<const float4*>(vgt)[idx];
                uint32_t h0, lo0, h1, lo1;
                split2(x.x, x.y, h0, lo0);
                split2(x.z, x.w, h1, lo1);
                *reinterpret_cast<uint2*>(smem + SM_VHI + so) = make_uint2(h0, h1);
                *reinterpret_cast<uint2*>(smem + SM_VLO + so) = make_uint2(lo0, lo1);
            }
        }
        const float* sgt = sg + (size_t)kt * kBK;
        #pragma unroll
        for (int it = 0; it < 8; ++it) {
            const int idx = it * kThreads + tid;           // 2048 float4
            const int r = idx >> 4, c4 = (idx & 15) << 2;
            *reinterpret_cast<float4*>(smem + SM_SC + (size_t)(r * kScStride + c4) * 4) =
                *reinterpret_cast<const float4*>(sgt + (size_t)r * kS + c4);
        }
        __syncthreads();

        // ---- S = Q K^T : 8 n-tiles of 8 kk-cols, 3-term compensation ----
        float sacc[8][4];
        #pragma unroll
        for (int n = 0; n < 8; ++n)
            #pragma unroll
            for (int c = 0; c < 4; ++c) sacc[n][c] = 0.f;

        #pragma unroll
        for (int ks = 0; ks < 8; ++ks) {
            uint32_t bhi[8][2], blo[8][2];
            #pragma unroll
            for (int p = 0; p < 4; ++p) {
                // K B-frag addr: kk = p*16 + b4*8 + w8, kcol = ks*16 + b3*8
                const uint32_t off = (uint32_t)((p * 16 + b4 * 8 + w8) * kKVStrideB
                                                + (ks * 16 + b3 * 8) * 2);
                ldsm_x4(bhi[2*p][0], bhi[2*p][1], bhi[2*p+1][0], bhi[2*p+1][1],
                        sb + SM_KHI + off);
                ldsm_x4(blo[2*p][0], blo[2*p][1], blo[2*p+1][0], blo[2*p+1][1],
                        sb + SM_KLO + off);
            }
            #pragma unroll
            for (int n = 0; n < 8; ++n) {
                mma_bf16(sacc[n], qhi[ks], bhi[n][0], bhi[n][1]);
                mma_bf16(sacc[n], qhi[ks], blo[n][0], blo[n][1]);
                mma_bf16(sacc[n], qlo[ks], bhi[n][0], bhi[n][1]);
            }
        }

        // ---- scale, online softmax (rows g and g+8 of this warp) ----
        const int r0 = wid * 16 + g;
        const char* sc0 = smem + SM_SC + (size_t)r0 * kScStride * 4 + (size_t)(2 * t) * 4;
        const char* sc1 = sc0 + (size_t)8 * kScStride * 4;
        float mx0 = -INFINITY, mx1 = -INFINITY;
        #pragma unroll
        for (int n = 0; n < 8; ++n) {
            const float2 s0 = *reinterpret_cast<const float2*>(sc0 + n * 32);
            const float2 s1 = *reinterpret_cast<const float2*>(sc1 + n * 32);
            sacc[n][0] *= s0.x; sacc[n][1] *= s0.y;
            sacc[n][2] *= s1.x; sacc[n][3] *= s1.y;
            mx0 = fmaxf(mx0, fmaxf(sacc[n][0], sacc[n][1]));
            mx1 = fmaxf(mx1, fmaxf(sacc[n][2], sacc[n][3]));
        }
        #pragma unroll
        for (int off = 1; off <= 2; off <<= 1) {
            mx0 = fmaxf(mx0, __shfl_xor_sync(0xffffffffu, mx0, off));
            mx1 = fmaxf(mx1, __shfl_xor_sync(0xffffffffu, mx1, off));
        }
        const float m0n = fmaxf(m0, mx0), m1n = fmaxf(m1, mx1);
        const float a0 = __expf(m0 - m0n), a1 = __expf(m1 - m1n);

        float sum0 = 0.f, sum1 = 0.f;
        #pragma unroll
        for (int n = 0; n < 8; ++n) {
            sacc[n][0] = __expf(sacc[n][0] - m0n);
            sacc[n][1] = __expf(sacc[n][1] - m0n);
            sacc[n][2] = __expf(sacc[n][2] - m1n);
            sacc[n][3] = __expf(sacc[n][3] - m1n);
            sum0 += sacc[n][0] + sacc[n][1];
            sum1 += sacc[n][2] + sacc[n][3];
        }
        #pragma unroll
        for (int off = 1; off <= 2; off <<= 1) {
            sum0 += __shfl_xor_sync(0xffffffffu, sum0, off);
            sum1 += __shfl_xor_sync(0xffffffffu, sum1, off);
        }
        l0 = l0 * a0 + sum0;  m0 = m0n;
        l1 = l1 * a1 + sum1;  m1 = m1n;

        // rescale O
        #pragma unroll
        for (int n = 0; n < 16; ++n) {
            oacc[n][0] *= a0; oacc[n][1] *= a0;
            oacc[n][2] *= a1; oacc[n][3] *= a1;
        }

        // ---- repack P (C-frag) -> A-frags, hi/lo ----
        uint32_t phi[4][4], plo[4][4];
        #pragma unroll
        for (int j = 0; j < 4; ++j) {
            split2(sacc[2*j][0],   sacc[2*j][1],   phi[j][0], plo[j][0]);
            split2(sacc[2*j][2],   sacc[2*j][3],   phi[j][1], plo[j][1]);
            split2(sacc[2*j+1][0], sacc[2*j+1][1], phi[j][2], plo[j][2]);
            split2(sacc[2*j+1][2], sacc[2*j+1][3], phi[j][3], plo[j][3]);
        }

        // ---- O += P V : V^T B-frags via ldmatrix.trans ----
        #pragma unroll
        for (int j = 0; j < 4; ++j) {
            #pragma unroll
            for (int pp = 0; pp < 8; ++pp) {
                // V addr: kk = j*16 + b3*8 + w8, dcol = pp*16 + b4*8
                const uint32_t off = (uint32_t)((j * 16 + b3 * 8 + w8) * kKVStrideB
                                                + (pp * 16 + b4 * 8) * 2);
                uint32_t vh0, vh1, vh2, vh3, vl0, vl1, vl2, vl3;
                ldsm_x4_t(vh0, vh1, vh2, vh3, sb + SM_VHI + off);
                ldsm_x4_t(vl0, vl1, vl2, vl3, sb + SM_VLO + off);
                mma_bf16(oacc[2*pp],   phi[j], vh0, vh1);
                mma_bf16(oacc[2*pp],   phi[j], vl0, vl1);
                mma_bf16(oacc[2*pp],   plo[j], vh0, vh1);
                mma_bf16(oacc[2*pp+1], phi[j], vh2, vh3);
                mma_bf16(oacc[2*pp+1], phi[j], vl2, vl3);
                mma_bf16(oacc[2*pp+1], plo[j], vh2, vh3);
            }
        }
    }

    // ---- epilogue ----
    const float dp = decode_scalar(dropout_p);
    const float inv0 = dp / l0, inv1 = dp / l1;
    const size_t row0 = (size_t)bh * kS + (size_t)qt * kBQ + (size_t)(wid * 16 + g);
    float* o0 = out + row0 * kD + 2 * t;
    float* o1 = o0 + (size_t)8 * kD;
    #pragma unroll
    for (int n = 0; n < 16; ++n) {
        *reinterpret_cast<float2*>(o0 + n * 8) = make_float2(oacc[n][0] * inv0, oacc[n][1] * inv0);
        *reinterpret_cast<float2*>(o1 + n * 8) = make_float2(oacc[n][2] * inv1, oacc[n][3] * inv1);
    }
}

extern "C" void kernel_launch(void* const* d_in, const int* in_sizes, int n_in,
                              void* d_out, int out_size) {
    const float* q  = (const float*)d_in[0];
    const float* k  = (const float*)d_in[1];
    const float* v  = (const float*)d_in[2];
    const float* sf = (const float*)d_in[3];
    const void*  dp = d_in[4];
    float* out = (float*)d_out;
    (void)in_sizes; (void)n_in; (void)out_size;

    cudaFuncSetAttribute(flash_mma_kernel,
                         cudaFuncAttributeMaxDynamicSharedMemorySize, kSmemBytes);
    dim3 grid(kS / kBQ, 32);   // 16 x 32 = 512 CTAs
    flash_mma_kernel<<<grid, kThreads, kSmemBytes>>>(q, k, v, sf, dp, out);
}

// round 4
// speedup vs baseline: 3.8564x; 1.1833x over previous
#include <cuda_runtime.h>
#include <cuda_bf16.h>
#include <cstdint>
#include <math.h>

// ============================================================
// R4: Flash attention, per-element scale, mma.sync m16n8k16 bf16
// hi/lo 3-term compensation. K/V pre-converted ONCE to padded
// smem tile images in __device__ scratch; main kernel streams
// them with cp.async (double-buffered), 1 syncthreads/iter.
// ============================================================

constexpr int kS = 2048, kD = 128, kBQ = 128, kBK = 64;
constexpr int kThreads = 256;
constexpr int kIters = kS / kBK;            // 32
constexpr int kQTiles = kS / kBQ;           // 16

constexpr int kKVStrideB = 272;             // 136 bf16 per row (pad for ldmatrix)
constexpr int kKVTileB   = 64 * kKVStrideB; // 17408
constexpr int kBlobB     = 4 * kKVTileB;    // khi,klo,vhi,vlo = 69632
constexpr int kScStrideB = 272;             // 68 floats
constexpr int kScTileB   = 128 * kScStrideB; // 34816

// smem: stage0 blob, stage1 blob, SC stage0, SC stage1
constexpr int SM_SC      = 2 * kBlobB;       // 139264
constexpr int kSmemBytes = SM_SC + 2 * kScTileB;  // 208896

// K/V pre-converted tile images: [bh][kt][blob 69632B]
__device__ __align__(16) unsigned char g_kv[32u * 32u * (unsigned)kBlobB];

__device__ __forceinline__ uint32_t smem_u32(const void* p) {
    uint32_t a;
    asm("{ .reg .u64 t; cvta.to.shared.u64 t, %1; cvt.u32.u64 %0, t; }" : "=r"(a) : "l"(p));
    return a;
}
__device__ __forceinline__ void cp16(uint32_t dst, const void* src) {
    asm volatile("cp.async.cg.shared.global [%0], [%1], 16;" :: "r"(dst), "l"(src));
}
__device__ __forceinline__ void cp_commit() {
    asm volatile("cp.async.commit_group;" ::: "memory");
}
__device__ __forceinline__ void cp_wait0() {
    asm volatile("cp.async.wait_group 0;" ::: "memory");
}
__device__ __forceinline__ void ldsm_x4(uint32_t& r0, uint32_t& r1, uint32_t& r2, uint32_t& r3,
                                        uint32_t addr) {
    asm volatile("ldmatrix.sync.aligned.m8n8.x4.shared.b16 {%0,%1,%2,%3}, [%4];"
        : "=r"(r0), "=r"(r1), "=r"(r2), "=r"(r3) : "r"(addr));
}
__device__ __forceinline__ void ldsm_x4_t(uint32_t& r0, uint32_t& r1, uint32_t& r2, uint32_t& r3,
                                          uint32_t addr) {
    asm volatile("ldmatrix.sync.aligned.m8n8.x4.trans.shared.b16 {%0,%1,%2,%3}, [%4];"
        : "=r"(r0), "=r"(r1), "=r"(r2), "=r"(r3) : "r"(addr));
}
__device__ __forceinline__ void mma_bf16(float* d, const uint32_t* a, uint32_t b0, uint32_t b1) {
    asm volatile("mma.sync.aligned.m16n8k16.row.col.f32.bf16.bf16.f32 "
        "{%0,%1,%2,%3}, {%4,%5,%6,%7}, {%8,%9}, {%0,%1,%2,%3};"
        : "+f"(d[0]), "+f"(d[1]), "+f"(d[2]), "+f"(d[3])
        : "r"(a[0]), "r"(a[1]), "r"(a[2]), "r"(a[3]), "r"(b0), "r"(b1));
}
__device__ __forceinline__ uint32_t packbf(float a, float b) {
    __nv_bfloat162 t = __floats2bfloat162_rn(a, b);
    return *reinterpret_cast<uint32_t*>(&t);
}
__device__ __forceinline__ void split2(float a, float b, uint32_t& hi, uint32_t& lo) {
    __nv_bfloat16 ah = __float2bfloat16(a), bh = __float2bfloat16(b);
    __nv_bfloat162 h; h.x = ah; h.y = bh;
    hi = *reinterpret_cast<uint32_t*>(&h);
    lo = packbf(a - __bfloat162float(ah), b - __bfloat162float(bh));
}
__device__ __forceinline__ float decode_scalar(const void* p) {
    const int w = *reinterpret_cast<const int*>(p);
    if (w > -(1 << 23) && w < (1 << 23)) return (float)w;
    return __int_as_float(w);
}

// ---------------- precompute: K,V -> bf16 hi/lo padded tile images ----------------
__global__ __launch_bounds__(256, 4)
void convert_kv_kernel(const float* __restrict__ k, const float* __restrict__ v) {
    const int kt = (int)blockIdx.x, bh = (int)blockIdx.y, tid = (int)threadIdx.x;
    unsigned char* blob = g_kv + (size_t)(bh * 32 + kt) * kBlobB;
    const float* kgt = k + ((size_t)bh * kS + (size_t)kt * kBK) * kD;
    const float* vgt = v + ((size_t)bh * kS + (size_t)kt * kBK) * kD;
    #pragma unroll
    for (int it = 0; it < 8; ++it) {
        const int idx = it * 256 + tid;            // 2048 float4 per tile
        const int r = idx >> 5, c = (idx & 31) << 2;
        const int so = r * kKVStrideB + c * 2;
        {
            const float4 x = reinterpret_cast<const float4*>(kgt)[idx];
            uint32_t h0, l0, h1, l1;
            split2(x.x, x.y, h0, l0);
            split2(x.z, x.w, h1, l1);
            *reinterpret_cast<uint2*>(blob + so)            = make_uint2(h0, h1);
            *reinterpret_cast<uint2*>(blob + kKVTileB + so) = make_uint2(l0, l1);
        }
        {
            const float4 x = reinterpret_cast<const float4*>(vgt)[idx];
            uint32_t h0, l0, h1, l1;
            split2(x.x, x.y, h0, l0);
            split2(x.z, x.w, h1, l1);
            *reinterpret_cast<uint2*>(blob + 2 * kKVTileB + so) = make_uint2(h0, h1);
            *reinterpret_cast<uint2*>(blob + 3 * kKVTileB + so) = make_uint2(l0, l1);
        }
    }
}

// ---------------- main kernel ----------------
__global__ __launch_bounds__(kThreads, 1)
void flash_mma_kernel(const float* __restrict__ q,
                      const float* __restrict__ sf,
                      const void*  __restrict__ dropout_p,
                      float* __restrict__ out) {
    extern __shared__ char smem[];
    const uint32_t sb = smem_u32(smem);
    const int tid  = (int)threadIdx.x;
    const int wid  = tid >> 5;
    const int lane = tid & 31;
    const int g    = lane >> 2;
    const int t    = lane & 3;
    const int qt = (int)blockIdx.x;
    const int bh = (int)blockIdx.y;

    const float* qg = q + ((size_t)bh * kS + (size_t)qt * kBQ) * kD;
    const float* sg = sf + (size_t)(qt * kBQ) * kS;

    // issue tile 0 cp.async before anything else
    auto issue_tile = [&](int kt, int stage) {
        const unsigned char* src = g_kv + (size_t)(bh * 32 + kt) * kBlobB;
        const uint32_t dkv = sb + (uint32_t)stage * kBlobB;
        #pragma unroll
        for (int i = 0; i < 17; ++i) {
            const int op = i * kThreads + tid;     // 4352 ops
            cp16(dkv + op * 16, src + (size_t)op * 16);
        }
        const unsigned char* ssc = reinterpret_cast<const unsigned char*>(sg + (size_t)kt * kBK);
        const uint32_t dsc = sb + SM_SC + (uint32_t)stage * kScTileB;
        #pragma unroll
        for (int i = 0; i < 8; ++i) {
            const int op = i * kThreads + tid;     // 2048 ops
            const int r = op >> 4, c = op & 15;
            cp16(dsc + (uint32_t)(r * kScStrideB + c * 16), ssc + (size_t)r * (kS * 4) + c * 16);
        }
        cp_commit();
    };
    issue_tile(0, 0);

    // ---- Q fragments (hi/lo) in registers ----
    uint32_t qhi[8][4], qlo[8][4];
    {
        const float* rq0 = qg + (size_t)(wid * 16 + g) * kD;
        const float* rq8 = rq0 + 8 * kD;
        #pragma unroll
        for (int ks = 0; ks < 8; ++ks) {
            const int c = ks * 16 + 2 * t;
            const float2 f0 = *reinterpret_cast<const float2*>(rq0 + c);
            const float2 f1 = *reinterpret_cast<const float2*>(rq8 + c);
            const float2 f2 = *reinterpret_cast<const float2*>(rq0 + c + 8);
            const float2 f3 = *reinterpret_cast<const float2*>(rq8 + c + 8);
            split2(f0.x, f0.y, qhi[ks][0], qlo[ks][0]);
            split2(f1.x, f1.y, qhi[ks][1], qlo[ks][1]);
            split2(f2.x, f2.y, qhi[ks][2], qlo[ks][2]);
            split2(f3.x, f3.y, qhi[ks][3], qlo[ks][3]);
        }
    }

    float oacc[16][4];
    #pragma unroll
    for (int n = 0; n < 16; ++n)
        #pragma unroll
        for (int c = 0; c < 4; ++c) oacc[n][c] = 0.f;
    float m0 = -INFINITY, m1 = -INFINITY, l0 = 0.f, l1 = 0.f;

    const int w8 = lane & 7;
    const int b3 = (lane >> 3) & 1;
    const int b4 = (lane >> 4) & 1;

    for (int kt = 0; kt < kIters; ++kt) {
        cp_wait0();
        __syncthreads();     // tile kt visible; all warps done with stage (kt+1)&1 from iter kt-1
        if (kt + 1 < kIters) issue_tile(kt + 1, (kt + 1) & 1);

        const int st = kt & 1;
        const uint32_t KHI = sb + (uint32_t)st * kBlobB;
        const uint32_t KLO = KHI + kKVTileB;
        const uint32_t VHI = KHI + 2 * kKVTileB;
        const uint32_t VLO = KHI + 3 * kKVTileB;

        // ---- S = Q K^T ----
        float sacc[8][4];
        #pragma unroll
        for (int n = 0; n < 8; ++n)
            #pragma unroll
            for (int c = 0; c < 4; ++c) sacc[n][c] = 0.f;

        #pragma unroll
        for (int ks = 0; ks < 8; ++ks) {
            uint32_t bhi[8][2], blo[8][2];
            #pragma unroll
            for (int p = 0; p < 4; ++p) {
                const uint32_t off = (uint32_t)((p * 16 + b4 * 8 + w8) * kKVStrideB
                                                + (ks * 16 + b3 * 8) * 2);
                ldsm_x4(bhi[2*p][0], bhi[2*p][1], bhi[2*p+1][0], bhi[2*p+1][1], KHI + off);
                ldsm_x4(blo[2*p][0], blo[2*p][1], blo[2*p+1][0], blo[2*p+1][1], KLO + off);
            }
            #pragma unroll
            for (int n = 0; n < 8; ++n) {
                mma_bf16(sacc[n], qhi[ks], bhi[n][0], bhi[n][1]);
                mma_bf16(sacc[n], qhi[ks], blo[n][0], blo[n][1]);
                mma_bf16(sacc[n], qlo[ks], bhi[n][0], bhi[n][1]);
            }
        }

        // ---- scale + online softmax ----
        const int r0 = wid * 16 + g;
        const char* scb = smem + SM_SC + (size_t)st * kScTileB;
        const char* sc0 = scb + (size_t)r0 * kScStrideB + (size_t)(2 * t) * 4;
        const char* sc1 = sc0 + (size_t)8 * kScStrideB;
        float mx0 = -INFINITY, mx1 = -INFINITY;
        #pragma unroll
        for (int n = 0; n < 8; ++n) {
            const float2 s0 = *reinterpret_cast<const float2*>(sc0 + n * 32);
            const float2 s1 = *reinterpret_cast<const float2*>(sc1 + n * 32);
            sacc[n][0] *= s0.x; sacc[n][1] *= s0.y;
            sacc[n][2] *= s1.x; sacc[n][3] *= s1.y;
            mx0 = fmaxf(mx0, fmaxf(sacc[n][0], sacc[n][1]));
            mx1 = fmaxf(mx1, fmaxf(sacc[n][2], sacc[n][3]));
        }
        #pragma unroll
        for (int off = 1; off <= 2; off <<= 1) {
            mx0 = fmaxf(mx0, __shfl_xor_sync(0xffffffffu, mx0, off));
            mx1 = fmaxf(mx1, __shfl_xor_sync(0xffffffffu, mx1, off));
        }
        const float m0n = fmaxf(m0, mx0), m1n = fmaxf(m1, mx1);
        const float a0 = __expf(m0 - m0n), a1 = __expf(m1 - m1n);

        float sum0 = 0.f, sum1 = 0.f;
        #pragma unroll
        for (int n = 0; n < 8; ++n) {
            sacc[n][0] = __expf(sacc[n][0] - m0n);
            sacc[n][1] = __expf(sacc[n][1] - m0n);
            sacc[n][2] = __expf(sacc[n][2] - m1n);
            sacc[n][3] = __expf(sacc[n][3] - m1n);
            sum0 += sacc[n][0] + sacc[n][1];
            sum1 += sacc[n][2] + sacc[n][3];
        }
        #pragma unroll
        for (int off = 1; off <= 2; off <<= 1) {
            sum0 += __shfl_xor_sync(0xffffffffu, sum0, off);
            sum1 += __shfl_xor_sync(0xffffffffu, sum1, off);
        }
        l0 = l0 * a0 + sum0;  m0 = m0n;
        l1 = l1 * a1 + sum1;  m1 = m1n;

        #pragma unroll
        for (int n = 0; n < 16; ++n) {
            oacc[n][0] *= a0; oacc[n][1] *= a0;
            oacc[n][2] *= a1; oacc[n][3] *= a1;
        }

        // ---- repack P -> A-frags (hi/lo) ----
        uint32_t phi[4][4], plo[4][4];
        #pragma unroll
        for (int j = 0; j < 4; ++j) {
            split2(sacc[2*j][0],   sacc[2*j][1],   phi[j][0], plo[j][0]);
            split2(sacc[2*j][2],   sacc[2*j][3],   phi[j][1], plo[j][1]);
            split2(sacc[2*j+1][0], sacc[2*j+1][1], phi[j][2], plo[j][2]);
            split2(sacc[2*j+1][2], sacc[2*j+1][3], phi[j][3], plo[j][3]);
        }

        // ---- O += P V ----
        #pragma unroll
        for (int j = 0; j < 4; ++j) {
            #pragma unroll
            for (int pp = 0; pp < 8; ++pp) {
                const uint32_t off = (uint32_t)((j * 16 + b3 * 8 + w8) * kKVStrideB
                                                + (pp * 16 + b4 * 8) * 2);
                uint32_t vh0, vh1, vh2, vh3, vl0, vl1, vl2, vl3;
                ldsm_x4_t(vh0, vh1, vh2, vh3, VHI + off);
                ldsm_x4_t(vl0, vl1, vl2, vl3, VLO + off);
                mma_bf16(oacc[2*pp],   phi[j], vh0, vh1);
                mma_bf16(oacc[2*pp],   phi[j], vl0, vl1);
                mma_bf16(oacc[2*pp],   plo[j], vh0, vh1);
                mma_bf16(oacc[2*pp+1], phi[j], vh2, vh3);
                mma_bf16(oacc[2*pp+1], phi[j], vl2, vl3);
                mma_bf16(oacc[2*pp+1], plo[j], vh2, vh3);
            }
        }
    }

    // ---- epilogue ----
    const float dp = decode_scalar(dropout_p);
    const float inv0 = dp / l0, inv1 = dp / l1;
    const size_t row0 = (size_t)bh * kS + (size_t)qt * kBQ + (size_t)(wid * 16 + g);
    float* o0 = out + row0 * kD + 2 * t;
    float* o1 = o0 + (size_t)8 * kD;
    #pragma unroll
    for (int n = 0; n < 16; ++n) {
        *reinterpret_cast<float2*>(o0 + n * 8) = make_float2(oacc[n][0] * inv0, oacc[n][1] * inv0);
        *reinterpret_cast<float2*>(o1 + n * 8) = make_float2(oacc[n][2] * inv1, oacc[n][3] * inv1);
    }
}

extern "C" void kernel_launch(void* const* d_in, const int* in_sizes, int n_in,
                              void* d_out, int out_size) {
    const float* q  = (const float*)d_in[0];
    const float* k  = (const float*)d_in[1];
    const float* v  = (const float*)d_in[2];
    const float* sf = (const float*)d_in[3];
    const void*  dp = d_in[4];
    float* out = (float*)d_out;
    (void)in_sizes; (void)n_in; (void)out_size;

    dim3 cgrid(kIters, 32);
    convert_kv_kernel<<<cgrid, 256>>>(k, v);

    cudaFuncSetAttribute(flash_mma_kernel,
                         cudaFuncAttributeMaxDynamicSharedMemorySize, kSmemBytes);
    dim3 grid(kQTiles, 32);   // 16 x 32 = 512 CTAs
    flash_mma_kernel<<<grid, kThreads, kSmemBytes>>>(q, sf, dp, out);
}